// round 11
// baseline (speedup 1.0000x reference)
#include <cuda_runtime.h>
#include <math.h>

#define IN_F   1024
#define OUT_F  512
#define BATCH  256
#define CAP    96
#define TLO    0.02f
#define THI    0.98f

// Transposed no_edge bit matrix: [i][o_word], bit = o&31. 64 KB.
__device__ unsigned g_maskT[IN_F * (OUT_F / 32)];

// ---------------------------------------------------------------------------
// no_edge = argmax(etc + gumbel(u)) == 1, i.e. (etc1+g1) > (etc0+g0) strictly
// (argmax tie -> index 0). g(u) = -log(-log(u+eps)+eps) is strictly
// increasing, so for etc0==etc1 this is exactly u1>u0; full gumbel math as
// the general fallback.
// ---------------------------------------------------------------------------
__device__ __forceinline__ bool no_edge_of(float e0, float e1, float u0, float u1) {
    if (e0 == e1) return u1 > u0;
    const float eps = 1e-10f;
    float g0 = -logf(-logf(u0 + eps) + eps);
    float g1 = -logf(-logf(u1 + eps) + eps);
    return (e1 + g1) > (e0 + g0);
}

// ---------------------------------------------------------------------------
// Mask build + bit transpose. Block = 32(o) x 64(i) tile (two 32x32
// subtiles); thread t: o_local = t>>3, i_local = (t&7)*4 in each subtile ->
// 8 upfront LDG.128 (MLP 8). Ballot-transpose to maskT words.
// ---------------------------------------------------------------------------
__global__ __launch_bounds__(256)
void fused_mask_kernel(const float* __restrict__ etc, const float* __restrict__ un) {
    __shared__ unsigned bits[64][33];   // [i_local][o_local], padded

    const int t    = threadIdx.x;
    const int lane = t & 31;
    const int w    = t >> 5;
    const int ow   = blockIdx.x & 15;   // o-word index (OUT_F/32)
    const int it   = blockIdx.x >> 4;   // 64-wide i-tile index (IN_F/64)

    const int o_local = t >> 3;
    const int i_local = (t & 7) << 2;
    const size_t gp0 = (size_t)(ow * 32 + o_local) * IN_F + (it * 64 + i_local);
    const size_t f0  = gp0 >> 1;        // float4 index (2 pairs per float4)
    const size_t f1  = f0 + 16;         // +32 i positions

    float4 ea0 = ((const float4*)etc)[f0];
    float4 eb0 = ((const float4*)etc)[f0 + 1];
    float4 ea1 = ((const float4*)etc)[f1];
    float4 eb1 = ((const float4*)etc)[f1 + 1];
    float4 ua0 = ((const float4*)un)[f0];
    float4 ub0 = ((const float4*)un)[f0 + 1];
    float4 ua1 = ((const float4*)un)[f1];
    float4 ub1 = ((const float4*)un)[f1 + 1];

    bits[i_local + 0][o_local]      = no_edge_of(ea0.x, ea0.y, ua0.x, ua0.y) ? 1u : 0u;
    bits[i_local + 1][o_local]      = no_edge_of(ea0.z, ea0.w, ua0.z, ua0.w) ? 1u : 0u;
    bits[i_local + 2][o_local]      = no_edge_of(eb0.x, eb0.y, ub0.x, ub0.y) ? 1u : 0u;
    bits[i_local + 3][o_local]      = no_edge_of(eb0.z, eb0.w, ub0.z, ub0.w) ? 1u : 0u;
    bits[i_local + 32 + 0][o_local] = no_edge_of(ea1.x, ea1.y, ua1.x, ua1.y) ? 1u : 0u;
    bits[i_local + 32 + 1][o_local] = no_edge_of(ea1.z, ea1.w, ua1.z, ua1.w) ? 1u : 0u;
    bits[i_local + 32 + 2][o_local] = no_edge_of(eb1.x, eb1.y, ub1.x, ub1.y) ? 1u : 0u;
    bits[i_local + 32 + 3][o_local] = no_edge_of(eb1.z, eb1.w, ub1.z, ub1.w) ? 1u : 0u;

    __syncthreads();

    #pragma unroll
    for (int r = 0; r < 8; r++) {
        const int i = (w << 3) + r;
        unsigned word = __ballot_sync(0xFFFFFFFFu, bits[i][lane] != 0u);
        if (lane == 0) g_maskT[(size_t)(it * 64 + i) * 16 + ow] = word;
    }
}

// ---------------------------------------------------------------------------
// Select: grid (BATCH, 2). Block (b, par): 256 outputs of one parity for
// batch b; thread t -> o = 2t+par. Pre-sync phase (overlaps the mask kernel
// under PDL): x row load + warp-ballot candidate extraction. Then
// cudaGridDependencySynchronize() before any g_maskT read; stage candidate
// mask rows to smem, scan with pure-LDS reads. Deterministic full-scan
// fallback (no unmasked candidate / overflow). Clamp to identity offsets
// (2 / -1) handles all-no-edge rows exactly.
// ---------------------------------------------------------------------------
__global__ __launch_bounds__(256)
void select_kernel(const float* __restrict__ x, float* __restrict__ out) {
    __shared__ float    xsh[IN_F];
    __shared__ float    cv[CAP];
    __shared__ int      ci[CAP];
    __shared__ unsigned cm[CAP][16];
    __shared__ int      n_s;

    const int t    = threadIdx.x;
    const int lane = t & 31;
    const int b    = blockIdx.x;
    const int par  = blockIdx.y;          // 0 = min side, 1 = max side
    if (t == 0) n_s = 0;
    __syncthreads();

    // ---- pre-sync: x staging + candidate extraction (mask-independent) ----
    float4 v4 = ((const float4*)(x + (size_t)b * IN_F))[t];
    ((float4*)xsh)[t] = v4;
    float vals[4] = {v4.x, v4.y, v4.z, v4.w};
    #pragma unroll
    for (int j = 0; j < 4; j++) {
        float v = vals[j];
        bool  c = par ? (v > THI) : (v < TLO);
        unsigned m = __ballot_sync(0xFFFFFFFFu, c);
        if (c) {
            int rank = __popc(m & ((1u << lane) - 1u));
            int base = 0;
            int lead = __ffs(m) - 1;
            if (lane == lead) base = atomicAdd(&n_s, __popc(m));
            base = __shfl_sync(m, base, lead);
            int p = base + rank;
            if (p < CAP) { cv[p] = v; ci[p] = 4 * t + j; }
        }
    }
    __syncthreads();

    // ---- wait for the mask kernel's stores to be visible (PDL) ----
    cudaGridDependencySynchronize();

    const int  n   = min(n_s, CAP);
    const bool ovf = (n_s > CAP);

    // Stage candidate mask rows: cm[c][0..15] = maskT row ci[c]
    for (int k = t; k < n * 16; k += 256) {
        int c = k >> 4;
        cm[c][k & 15] = __ldg(&g_maskT[(size_t)ci[c] * 16 + (k & 15)]);
    }
    __syncthreads();

    const int o  = 2 * t + par;
    const int wo = o >> 5, bo = o & 31;
    const float INF  = __int_as_float(0x7F800000);
    const float NINF = __int_as_float(0xFF800000);
    const float init = par ? NINF : INF;

    float acc = init;
    if (!ovf) {
        if (par) {
            #pragma unroll 8
            for (int c = 0; c < n; c++) {
                unsigned wd = cm[c][wo];
                if (!((wd >> bo) & 1u)) acc = fmaxf(acc, cv[c]);
            }
        } else {
            #pragma unroll 8
            for (int c = 0; c < n; c++) {
                unsigned wd = cm[c][wo];
                if (!((wd >> bo) & 1u)) acc = fminf(acc, cv[c]);
            }
        }
    }
    if (acc == init) {   // no unmasked candidate (or overflow): full scan
        const unsigned* __restrict__ mt = g_maskT;
        if (par) {
            for (int i = 0; i < IN_F; i++) {
                unsigned wd = __ldg(&mt[(size_t)i * 16 + wo]);
                if (!((wd >> bo) & 1u)) acc = fmaxf(acc, xsh[i]);
            }
        } else {
            for (int i = 0; i < IN_F; i++) {
                unsigned wd = __ldg(&mt[(size_t)i * 16 + wo]);
                if (!((wd >> bo) & 1u)) acc = fminf(acc, xsh[i]);
            }
        }
    }

    float r = par ? fmaxf(acc, -1.0f) : fminf(acc, 2.0f);
    out[(size_t)b * OUT_F + o] = r;
}

extern "C" void kernel_launch(void* const* d_in, const int* in_sizes, int n_in,
                              void* d_out, int out_size) {
    const float* x   = (const float*)d_in[0];  // [256, 1024]
    const float* etc = (const float*)d_in[1];  // [512, 1024, 2]
    const float* un  = (const float*)d_in[2];  // [512, 1024, 2]
    float* out = (float*)d_out;                // [256, 512]

    fused_mask_kernel<<<(OUT_F / 32) * (IN_F / 64), 256>>>(etc, un);  // 256 blocks

    // Select with programmatic dependent launch: pre-sync phase overlaps the
    // mask kernel; cudaGridDependencySynchronize() gates maskT reads.
    cudaLaunchConfig_t cfg = {};
    cfg.gridDim  = dim3(BATCH, 2, 1);
    cfg.blockDim = dim3(256, 1, 1);
    cudaLaunchAttribute attr[1];
    attr[0].id = cudaLaunchAttributeProgrammaticStreamSerialization;
    attr[0].val.programmaticStreamSerializationAllowed = 1;
    cfg.attrs = attr;
    cfg.numAttrs = 1;
    cudaError_t e = cudaLaunchKernelEx(&cfg, select_kernel, x, out);
    if (e != cudaSuccess) {
        // PDL unsupported in this context: clear the error, launch plainly.
        (void)cudaGetLastError();
        dim3 sgrid(BATCH, 2);
        select_kernel<<<sgrid, 256>>>(x, out);
    }
}

// round 12
// speedup vs baseline: 1.3161x; 1.3161x over previous
#include <cuda_runtime.h>
#include <math.h>

#define IN_F   1024
#define OUT_F  512
#define BATCH  256
#define CAP    96
#define TLO    0.02f
#define THI    0.98f

// Transposed no_edge bit matrix: [i][o_word], bit = o&31. 64 KB.
__device__ unsigned g_maskT[IN_F * (OUT_F / 32)];

// ---------------------------------------------------------------------------
// no_edge = argmax(etc + gumbel(u)) == 1, i.e. (etc1+g1) > (etc0+g0) strictly
// (argmax tie -> index 0). g(u) = -log(-log(u+eps)+eps) is strictly
// increasing, so for etc0==etc1 this is exactly u1>u0; full gumbel math as
// the general fallback.
// ---------------------------------------------------------------------------
__device__ __forceinline__ bool no_edge_of(float e0, float e1, float u0, float u1) {
    if (e0 == e1) return u1 > u0;
    const float eps = 1e-10f;
    float g0 = -logf(-logf(u0 + eps) + eps);
    float g1 = -logf(-logf(u1 + eps) + eps);
    return (e1 + g1) > (e0 + g0);
}

// ---------------------------------------------------------------------------
// Mask build + bit transpose. Block = 32(o) x 64(i) tile (two 32x32
// subtiles); thread t: o_local = t>>3, i_local = (t&7)*4 in each subtile ->
// 8 upfront LDG.128 (MLP 8). Ballot-transpose to maskT words.
// ---------------------------------------------------------------------------
__global__ __launch_bounds__(256)
void fused_mask_kernel(const float* __restrict__ etc, const float* __restrict__ un) {
    __shared__ unsigned bits[64][33];   // [i_local][o_local], padded

    const int t    = threadIdx.x;
    const int lane = t & 31;
    const int w    = t >> 5;
    const int ow   = blockIdx.x & 15;   // o-word index (OUT_F/32)
    const int it   = blockIdx.x >> 4;   // 64-wide i-tile index (IN_F/64)

    const int o_local = t >> 3;
    const int i_local = (t & 7) << 2;
    const size_t gp0 = (size_t)(ow * 32 + o_local) * IN_F + (it * 64 + i_local);
    const size_t f0  = gp0 >> 1;        // float4 index (2 pairs per float4)
    const size_t f1  = f0 + 16;         // +32 i positions

    float4 ea0 = ((const float4*)etc)[f0];
    float4 eb0 = ((const float4*)etc)[f0 + 1];
    float4 ea1 = ((const float4*)etc)[f1];
    float4 eb1 = ((const float4*)etc)[f1 + 1];
    float4 ua0 = ((const float4*)un)[f0];
    float4 ub0 = ((const float4*)un)[f0 + 1];
    float4 ua1 = ((const float4*)un)[f1];
    float4 ub1 = ((const float4*)un)[f1 + 1];

    bits[i_local + 0][o_local]      = no_edge_of(ea0.x, ea0.y, ua0.x, ua0.y) ? 1u : 0u;
    bits[i_local + 1][o_local]      = no_edge_of(ea0.z, ea0.w, ua0.z, ua0.w) ? 1u : 0u;
    bits[i_local + 2][o_local]      = no_edge_of(eb0.x, eb0.y, ub0.x, ub0.y) ? 1u : 0u;
    bits[i_local + 3][o_local]      = no_edge_of(eb0.z, eb0.w, ub0.z, ub0.w) ? 1u : 0u;
    bits[i_local + 32 + 0][o_local] = no_edge_of(ea1.x, ea1.y, ua1.x, ua1.y) ? 1u : 0u;
    bits[i_local + 32 + 1][o_local] = no_edge_of(ea1.z, ea1.w, ua1.z, ua1.w) ? 1u : 0u;
    bits[i_local + 32 + 2][o_local] = no_edge_of(eb1.x, eb1.y, ub1.x, ub1.y) ? 1u : 0u;
    bits[i_local + 32 + 3][o_local] = no_edge_of(eb1.z, eb1.w, ub1.z, ub1.w) ? 1u : 0u;

    __syncthreads();

    #pragma unroll
    for (int r = 0; r < 8; r++) {
        const int i = (w << 3) + r;
        unsigned word = __ballot_sync(0xFFFFFFFFu, bits[i][lane] != 0u);
        if (lane == 0) g_maskT[(size_t)(it * 64 + i) * 16 + ow] = word;
    }
}

// ---------------------------------------------------------------------------
// Select: grid (BATCH, 2). Block (b, par) resolves the 256 outputs of one
// parity for batch b; thread t -> output o = 2t+par. par 0 = t-norm (min),
// par 1 = t-conorm (max).
// The extremum over ~512 unmasked uniform[0,1] values lies below TLO (min) /
// above THI (max) except with prob ~3e-5. Extract candidates via warp-ballot
// compaction, cooperatively stage their 16-word mask rows into smem, then
// each thread scans the candidate list with pure-LDS reads (broadcast,
// conflict-free). Deterministic full-scan fallback if no unmasked candidate
// or list overflow. Clamp to identity offsets (2 / -1) handles all-no-edge
// rows exactly.
// ---------------------------------------------------------------------------
__global__ __launch_bounds__(256)
void select_kernel(const float* __restrict__ x, float* __restrict__ out) {
    __shared__ float    xsh[IN_F];
    __shared__ float    cv[CAP];
    __shared__ int      ci[CAP];
    __shared__ unsigned cm[CAP][16];
    __shared__ int      n_s;

    const int t    = threadIdx.x;
    const int lane = t & 31;
    const int b    = blockIdx.x;
    const int par  = blockIdx.y;          // 0 = min side, 1 = max side
    if (t == 0) n_s = 0;
    __syncthreads();

    // Stage x row (coalesced float4), extract this parity's candidates
    float4 v4 = ((const float4*)(x + (size_t)b * IN_F))[t];
    ((float4*)xsh)[t] = v4;
    float vals[4] = {v4.x, v4.y, v4.z, v4.w};
    #pragma unroll
    for (int j = 0; j < 4; j++) {
        float v = vals[j];
        bool  c = par ? (v > THI) : (v < TLO);
        unsigned m = __ballot_sync(0xFFFFFFFFu, c);
        if (c) {
            int rank = __popc(m & ((1u << lane) - 1u));
            int base = 0;
            int lead = __ffs(m) - 1;
            if (lane == lead) base = atomicAdd(&n_s, __popc(m));
            base = __shfl_sync(m, base, lead);
            int p = base + rank;
            if (p < CAP) { cv[p] = v; ci[p] = 4 * t + j; }
        }
    }
    __syncthreads();

    const int  n   = min(n_s, CAP);
    const bool ovf = (n_s > CAP);

    // Cooperatively stage candidate mask rows: cm[c][0..15] = maskT row ci[c]
    for (int k = t; k < n * 16; k += 256) {
        int c = k >> 4;
        cm[c][k & 15] = __ldg(&g_maskT[(size_t)ci[c] * 16 + (k & 15)]);
    }
    __syncthreads();

    const int o  = 2 * t + par;
    const int wo = o >> 5, bo = o & 31;
    const float INF  = __int_as_float(0x7F800000);
    const float NINF = __int_as_float(0xFF800000);
    const float init = par ? NINF : INF;

    float acc = init;
    if (!ovf) {
        if (par) {
            #pragma unroll 8
            for (int c = 0; c < n; c++) {
                unsigned wd = cm[c][wo];
                if (!((wd >> bo) & 1u)) acc = fmaxf(acc, cv[c]);
            }
        } else {
            #pragma unroll 8
            for (int c = 0; c < n; c++) {
                unsigned wd = cm[c][wo];
                if (!((wd >> bo) & 1u)) acc = fminf(acc, cv[c]);
            }
        }
    }
    if (acc == init) {   // no unmasked candidate (or overflow): full scan
        const unsigned* __restrict__ mt = g_maskT;
        if (par) {
            for (int i = 0; i < IN_F; i++) {
                unsigned wd = __ldg(&mt[(size_t)i * 16 + wo]);
                if (!((wd >> bo) & 1u)) acc = fmaxf(acc, xsh[i]);
            }
        } else {
            for (int i = 0; i < IN_F; i++) {
                unsigned wd = __ldg(&mt[(size_t)i * 16 + wo]);
                if (!((wd >> bo) & 1u)) acc = fminf(acc, xsh[i]);
            }
        }
    }

    float r = par ? fmaxf(acc, -1.0f) : fminf(acc, 2.0f);
    out[(size_t)b * OUT_F + o] = r;
}

extern "C" void kernel_launch(void* const* d_in, const int* in_sizes, int n_in,
                              void* d_out, int out_size) {
    const float* x   = (const float*)d_in[0];  // [256, 1024]
    const float* etc = (const float*)d_in[1];  // [512, 1024, 2]
    const float* un  = (const float*)d_in[2];  // [512, 1024, 2]
    float* out = (float*)d_out;                // [256, 512]

    fused_mask_kernel<<<(OUT_F / 32) * (IN_F / 64), 256>>>(etc, un);  // 256 blocks
    dim3 sgrid(BATCH, 2);                                             // 512 blocks
    select_kernel<<<sgrid, 256>>>(x, out);
}

// round 13
// speedup vs baseline: 3.1075x; 2.3612x over previous
#include <cuda_runtime.h>
#include <math.h>

#define IN_F   1024
#define OUT_F  512
#define BATCH  256
#define CAP    96
#define TLO    0.04f
#define THI    0.96f

// Transposed no_edge bit matrix: [i][o_word], bit = o&31. 64 KB.
__device__ unsigned g_maskT[IN_F * (OUT_F / 32)];

// ---------------------------------------------------------------------------
// no_edge = argmax(etc + gumbel(u)) == 1, i.e. (etc1+g1) > (etc0+g0) strictly
// (argmax tie -> index 0). g(u) = -log(-log(u+eps)+eps) is strictly
// increasing, so for etc0==etc1 this is exactly u1>u0; full gumbel math as
// the general fallback.
// ---------------------------------------------------------------------------
__device__ __forceinline__ bool no_edge_of(float e0, float e1, float u0, float u1) {
    if (e0 == e1) return u1 > u0;
    const float eps = 1e-10f;
    float g0 = -logf(-logf(u0 + eps) + eps);
    float g1 = -logf(-logf(u1 + eps) + eps);
    return (e1 + g1) > (e0 + g0);
}

// ---------------------------------------------------------------------------
// Mask build + bit transpose (unchanged from R9). Block = 32(o) x 64(i) tile;
// 8 upfront LDG.128 per thread (MLP 8); ballot-transpose to maskT words.
// ---------------------------------------------------------------------------
__global__ __launch_bounds__(256)
void fused_mask_kernel(const float* __restrict__ etc, const float* __restrict__ un) {
    __shared__ unsigned bits[64][33];

    const int t    = threadIdx.x;
    const int lane = t & 31;
    const int w    = t >> 5;
    const int ow   = blockIdx.x & 15;
    const int it   = blockIdx.x >> 4;

    const int o_local = t >> 3;
    const int i_local = (t & 7) << 2;
    const size_t gp0 = (size_t)(ow * 32 + o_local) * IN_F + (it * 64 + i_local);
    const size_t f0  = gp0 >> 1;
    const size_t f1  = f0 + 16;

    float4 ea0 = ((const float4*)etc)[f0];
    float4 eb0 = ((const float4*)etc)[f0 + 1];
    float4 ea1 = ((const float4*)etc)[f1];
    float4 eb1 = ((const float4*)etc)[f1 + 1];
    float4 ua0 = ((const float4*)un)[f0];
    float4 ub0 = ((const float4*)un)[f0 + 1];
    float4 ua1 = ((const float4*)un)[f1];
    float4 ub1 = ((const float4*)un)[f1 + 1];

    bits[i_local + 0][o_local]      = no_edge_of(ea0.x, ea0.y, ua0.x, ua0.y) ? 1u : 0u;
    bits[i_local + 1][o_local]      = no_edge_of(ea0.z, ea0.w, ua0.z, ua0.w) ? 1u : 0u;
    bits[i_local + 2][o_local]      = no_edge_of(eb0.x, eb0.y, ub0.x, ub0.y) ? 1u : 0u;
    bits[i_local + 3][o_local]      = no_edge_of(eb0.z, eb0.w, ub0.z, ub0.w) ? 1u : 0u;
    bits[i_local + 32 + 0][o_local] = no_edge_of(ea1.x, ea1.y, ua1.x, ua1.y) ? 1u : 0u;
    bits[i_local + 32 + 1][o_local] = no_edge_of(ea1.z, ea1.w, ua1.z, ua1.w) ? 1u : 0u;
    bits[i_local + 32 + 2][o_local] = no_edge_of(eb1.x, eb1.y, ub1.x, ub1.y) ? 1u : 0u;
    bits[i_local + 32 + 3][o_local] = no_edge_of(eb1.z, eb1.w, ub1.z, ub1.w) ? 1u : 0u;

    __syncthreads();

    #pragma unroll
    for (int r = 0; r < 8; r++) {
        const int i = (w << 3) + r;
        unsigned word = __ballot_sync(0xFFFFFFFFu, bits[i][lane] != 0u);
        if (lane == 0) g_maskT[(size_t)(it * 64 + i) * 16 + ow] = word;
    }
}

// ---------------------------------------------------------------------------
// Select: one block per batch, 512 threads. t<256: min outputs o=2t;
// t>=256: max outputs o=2(t-256)+1 (warp-uniform sides).
// Extract candidates (x<TLO / x>THI) once for both sides, rank-sort each
// list by value (index tiebreak -> exact permutation), stage mask rows in
// sorted order, then each thread takes the FIRST unmasked candidate = exact
// extremum. Deterministic unrolled full-scan fallback (prob ~1e-9/output).
// Clamp to identity offsets (2 / -1) handles all-no-edge rows exactly.
// ---------------------------------------------------------------------------
__global__ __launch_bounds__(512)
void select_kernel(const float* __restrict__ x, float* __restrict__ out) {
    __shared__ float    xsh[IN_F];
    __shared__ float    cv[2][CAP];
    __shared__ int      ci[2][CAP];
    __shared__ float    sv[2][CAP];
    __shared__ int      sci[2][CAP];
    __shared__ unsigned cm[2][CAP][16];
    __shared__ float    so_out[OUT_F];
    __shared__ int      n_s[2];

    const int t    = threadIdx.x;
    const int lane = t & 31;
    const int b    = blockIdx.x;
    if (t == 0) { n_s[0] = 0; n_s[1] = 0; }
    __syncthreads();

    // ---- stage x row (float2/thread), extract both candidate lists ----
    float2 v2 = ((const float2*)(x + (size_t)b * IN_F))[t];
    ((float2*)xsh)[t] = v2;
    float vals[2] = {v2.x, v2.y};
    #pragma unroll
    for (int j = 0; j < 2; j++) {
        float v = vals[j];
        int   i = 2 * t + j;

        unsigned mlo = __ballot_sync(0xFFFFFFFFu, v < TLO);
        if (v < TLO) {
            int rank = __popc(mlo & ((1u << lane) - 1u));
            int base = 0, lead = __ffs(mlo) - 1;
            if (lane == lead) base = atomicAdd(&n_s[0], __popc(mlo));
            base = __shfl_sync(mlo, base, lead);
            int p = base + rank;
            if (p < CAP) { cv[0][p] = v; ci[0][p] = i; }
        }
        unsigned mhi = __ballot_sync(0xFFFFFFFFu, v > THI);
        if (v > THI) {
            int rank = __popc(mhi & ((1u << lane) - 1u));
            int base = 0, lead = __ffs(mhi) - 1;
            if (lane == lead) base = atomicAdd(&n_s[1], __popc(mhi));
            base = __shfl_sync(mhi, base, lead);
            int p = base + rank;
            if (p < CAP) { cv[1][p] = v; ci[1][p] = i; }
        }
    }
    __syncthreads();

    const int side = t >> 8;        // 0 = min side, 1 = max side
    const int tl   = t & 255;
    const int n0   = min(n_s[0], CAP);
    const int n1   = min(n_s[1], CAP);
    const int n    = side ? n1 : n0;
    const bool ovf = (n_s[side] > CAP);

    // ---- rank-sort: ascending for min list, descending for max list ----
    if (tl < n) {
        float vme = cv[side][tl];
        int r = 0;
        if (side == 0) {
            for (int j = 0; j < n; j++) {
                float vj = cv[0][j];
                r += (vj < vme) || (vj == vme && j < tl);
            }
        } else {
            for (int j = 0; j < n; j++) {
                float vj = cv[1][j];
                r += (vj > vme) || (vj == vme && j < tl);
            }
        }
        sv[side][r]  = vme;
        sci[side][r] = ci[side][tl];
    }
    __syncthreads();

    // ---- stage mask rows in sorted order (cooperative, both lists) ----
    for (int k = t; k < n0 * 16; k += 512) {
        int c = k >> 4;
        cm[0][c][k & 15] = __ldg(&g_maskT[(size_t)sci[0][c] * 16 + (k & 15)]);
    }
    for (int k = t; k < n1 * 16; k += 512) {
        int c = k >> 4;
        cm[1][c][k & 15] = __ldg(&g_maskT[(size_t)sci[1][c] * 16 + (k & 15)]);
    }
    __syncthreads();

    // ---- resolve: first unmasked candidate in sorted order ----
    const int o  = 2 * tl + side;
    const int wo = o >> 5, bo = o & 31;
    const float INF  = __int_as_float(0x7F800000);
    const float NINF = __int_as_float(0xFF800000);
    const float init = side ? NINF : INF;

    float acc = init;
    if (!ovf) {
        for (int c = 0; c < n; c++) {
            unsigned wd = cm[side][c][wo];
            if (!((wd >> bo) & 1u)) { acc = sv[side][c]; break; }
        }
    }
    if (acc == init) {   // no unmasked candidate (or overflow): full scan, MLP 8
        const unsigned* __restrict__ mt = g_maskT;
        if (side) {
            for (int i = 0; i < IN_F; i += 8) {
                #pragma unroll
                for (int u = 0; u < 8; u++) {
                    unsigned wd = __ldg(&mt[(size_t)(i + u) * 16 + wo]);
                    if (!((wd >> bo) & 1u)) acc = fmaxf(acc, xsh[i + u]);
                }
            }
        } else {
            for (int i = 0; i < IN_F; i += 8) {
                #pragma unroll
                for (int u = 0; u < 8; u++) {
                    unsigned wd = __ldg(&mt[(size_t)(i + u) * 16 + wo]);
                    if (!((wd >> bo) & 1u)) acc = fminf(acc, xsh[i + u]);
                }
            }
        }
    }

    so_out[o] = side ? fmaxf(acc, -1.0f) : fminf(acc, 2.0f);
    __syncthreads();

    // ---- coalesced float4 store ----
    if (t < OUT_F / 4) {
        ((float4*)(out + (size_t)b * OUT_F))[t] = ((const float4*)so_out)[t];
    }
}

extern "C" void kernel_launch(void* const* d_in, const int* in_sizes, int n_in,
                              void* d_out, int out_size) {
    const float* x   = (const float*)d_in[0];  // [256, 1024]
    const float* etc = (const float*)d_in[1];  // [512, 1024, 2]
    const float* un  = (const float*)d_in[2];  // [512, 1024, 2]
    float* out = (float*)d_out;                // [256, 512]

    fused_mask_kernel<<<(OUT_F / 32) * (IN_F / 64), 256>>>(etc, un);  // 256 blocks
    select_kernel<<<BATCH, 512>>>(x, out);                            // 256 blocks
}